// round 17
// baseline (speedup 1.0000x reference)
#include <cuda_runtime.h>
#include <cuda_fp16.h>
#include <math.h>

#define B 64
#define S 512
#define H 512
#define E 512
#define NSEG 64
#define MR (B*S)
#define NPROJ 3072
#define POOL (B*NSEG*2*H)
#define NBLK 64

__device__ __align__(16) float g_X[(size_t)MR*E];
__device__ __align__(16) float g_XP[(size_t)MR*NPROJ];
__device__ __align__(16) float g_ctx[(size_t)MR*2*H];
__device__ __align__(16) __half g_ht16[2][2][B][H];  // [buf][dir][batch][col]
__device__ unsigned long long g_bar;

__device__ __forceinline__ void gbar(){
  __threadfence();
  __syncthreads();
  if (threadIdx.x == 0){
    unsigned long long t = atomicAdd(&g_bar, 1ULL);
    unsigned long long target = (t/(unsigned long long)NBLK + 1ULL)*(unsigned long long)NBLK;
    while (*(volatile unsigned long long*)&g_bar < target) __nanosleep(16);
  }
  __syncthreads();
}

__device__ __forceinline__ unsigned tf(float x){
  unsigned u; asm("cvt.rna.tf32.f32 %0, %1;" : "=r"(u) : "f"(x));
  return u;
}
__device__ __forceinline__ void mma8(float c[4], const unsigned a[4], const unsigned b[2]){
  asm volatile("mma.sync.aligned.m16n8k8.row.col.f32.tf32.tf32.f32 "
    "{%0,%1,%2,%3}, {%4,%5,%6,%7}, {%8,%9}, {%0,%1,%2,%3};"
    : "+f"(c[0]), "+f"(c[1]), "+f"(c[2]), "+f"(c[3])
    : "r"(a[0]), "r"(a[1]), "r"(a[2]), "r"(a[3]), "r"(b[0]), "r"(b[1]));
}
__device__ __forceinline__ void mma16(float c[4], const unsigned a[4], const unsigned b[2]){
  asm volatile("mma.sync.aligned.m16n8k16.row.col.f32.f16.f16.f32 "
    "{%0,%1,%2,%3}, {%4,%5,%6,%7}, {%8,%9}, {%0,%1,%2,%3};"
    : "+f"(c[0]), "+f"(c[1]), "+f"(c[2]), "+f"(c[3])
    : "r"(a[0]), "r"(a[1]), "r"(a[2]), "r"(a[3]), "r"(b[0]), "r"(b[1]));
}
__device__ __forceinline__ void cpasync16(unsigned saddr, const void* g){
  asm volatile("cp.async.cg.shared.global [%0], [%1], 16;" :: "r"(saddr), "l"(g) : "memory");
}

__global__ void k_embed(const int* __restrict__ seq, const float* __restrict__ emb){
  size_t i = (size_t)blockIdx.x*256 + threadIdx.x;
  int c = (int)(i & 127); size_t row = i >> 7;
  int tok = seq[row];
  reinterpret_cast<float4*>(g_X)[row*128 + c] =
      reinterpret_cast<const float4*>(emb)[(size_t)tok*128 + c];
}

__global__ void __launch_bounds__(256) k_gemm(
    const float* __restrict__ wf, const float* __restrict__ wb,
    const float* __restrict__ bf, const float* __restrict__ bb){
  __shared__ __align__(16) float sA[128*36];
  __shared__ __align__(16) float sB[64*36];
  int nb = blockIdx.x, mb = blockIdx.y;
  const float* W; const float* bias; int nloc;
  if (nb < 24){ W = wf; bias = bf; nloc = nb*64; }
  else        { W = wb; bias = bb; nloc = (nb-24)*64; }
  int tid = threadIdx.x, lane = tid & 31, warp = tid >> 5;
  int wM = warp & 3, wN = warp >> 2;
  float acc[2][4][4];
  #pragma unroll
  for (int i=0;i<2;i++)
    #pragma unroll
    for (int j=0;j<4;j++)
      #pragma unroll
      for (int k=0;k<4;k++) acc[i][j][k]=0.f;
  const float4* X4 = reinterpret_cast<const float4*>(g_X);
  const float4* W4 = reinterpret_cast<const float4*>(W);
  for (int kt = 0; kt < 16; kt++){
    float4 av[4], bv[2];
    #pragma unroll
    for (int it=0; it<4; it++){
      int idx = tid + it*256, r = idx>>3, c4 = idx&7;
      av[it] = X4[((size_t)(mb*128+r))*128 + kt*8 + c4];
    }
    #pragma unroll
    for (int it=0; it<2; it++){
      int idx = tid + it*256, r = idx>>3, c4 = idx&7;
      bv[it] = W4[((size_t)(nloc+r))*128 + kt*8 + c4];
    }
    __syncthreads();
    unsigned* uA = (unsigned*)sA; unsigned* uB = (unsigned*)sB;
    #pragma unroll
    for (int it=0; it<4; it++){
      int idx = tid + it*256, r = idx>>3, c4 = idx&7;
      unsigned* d = uA + r*36 + c4*4;
      d[0]=tf(av[it].x); d[1]=tf(av[it].y); d[2]=tf(av[it].z); d[3]=tf(av[it].w);
    }
    #pragma unroll
    for (int it=0; it<2; it++){
      int idx = tid + it*256, r = idx>>3, c4 = idx&7;
      unsigned* d = uB + r*36 + c4*4;
      d[0]=tf(bv[it].x); d[1]=tf(bv[it].y); d[2]=tf(bv[it].z); d[3]=tf(bv[it].w);
    }
    __syncthreads();
    #pragma unroll
    for (int ks=0; ks<4; ks++){
      int kb = ks*8;
      unsigned afr[2][4], bfr[4][2];
      #pragma unroll
      for (int wm=0; wm<2; wm++){
        int r = wM*32 + wm*16 + (lane>>2), c = kb + (lane&3);
        afr[wm][0] = uA[r*36 + c];       afr[wm][1] = uA[(r+8)*36 + c];
        afr[wm][2] = uA[r*36 + c + 4];   afr[wm][3] = uA[(r+8)*36 + c + 4];
      }
      #pragma unroll
      for (int wn=0; wn<4; wn++){
        int nr = wN*32 + wn*8 + (lane>>2), c = kb + (lane&3);
        bfr[wn][0] = uB[nr*36 + c]; bfr[wn][1] = uB[nr*36 + c + 4];
      }
      #pragma unroll
      for (int wm=0; wm<2; wm++)
        #pragma unroll
        for (int wn=0; wn<4; wn++) mma8(acc[wm][wn], afr[wm], bfr[wn]);
    }
    __syncthreads();
  }
  #pragma unroll
  for (int wm=0; wm<2; wm++){
    int r0 = mb*128 + wM*32 + wm*16 + (lane>>2);
    #pragma unroll
    for (int wn=0; wn<4; wn++){
      int cl = wN*32 + wn*8 + (lane&3)*2;
      int cg = nb*64 + cl;
      float b0v = bias[nloc + cl], b1v = bias[nloc + cl + 1];
      float2 v0 = make_float2(acc[wm][wn][0]+b0v, acc[wm][wn][1]+b1v);
      float2 v1 = make_float2(acc[wm][wn][2]+b0v, acc[wm][wn][3]+b1v);
      *(float2*)&g_XP[(size_t)r0*NPROJ + cg] = v0;
      *(float2*)&g_XP[(size_t)(r0+8)*NPROJ + cg] = v1;
    }
  }
}

// Persistent bidirectional GRU scan, both directions fused per block.
// 64 blocks (one per 8-col chunk), 768 threads = 24 warps (12 per dir).
// smem halfs: sW16[2][24*520] | sH16[2][64*520] | floats sG[2][64*26]
__global__ void __launch_bounds__(768, 1) k_scan(
    const int* __restrict__ lens,
    const float* __restrict__ whf, const float* __restrict__ whb,
    const float* __restrict__ bhf, const float* __restrict__ bhb,
    float* __restrict__ out){
  extern __shared__ __align__(16) char smraw[];
  __half* sW16 = (__half*)smraw;            // 2*24*520
  __half* sH16 = sW16 + 2*24*520;           // 2*64*520
  float*  sG   = (float*)(sH16 + 2*64*520); // 2*64*26
  int chunk = blockIdx.x;
  int j0 = chunk*8;
  int tid = threadIdx.x;
  // load both W slices (fp16)
  for (int idx = tid; idx < 2*24*512; idx += 768){
    int d = idx >> 13;             // 24*512 = 12288 = 3*2^12 ... use explicit div
    int rem = idx - d*12288;
    d = idx / 12288; rem = idx - d*12288;
    int r = rem >> 9, k = rem & 511;
    const float* Wh = d ? whb : whf;
    sW16[d*24*520 + r*520 + k] = __float2half(Wh[(size_t)((r>>3)*512 + j0 + (r&7))*512 + k]);
  }
  for (int idx = tid; idx < 2048; idx += 768){
    int buf = idx >> 10, d = (idx >> 9) & 1, jl = (idx >> 6) & 7, bb = idx & 63;
    g_ht16[buf][d][bb][j0+jl] = __float2half(0.f);
  }
  // mma identities
  int warp = tid >> 5, lane = tid & 31;
  int wdir = (warp >= 12) ? 1 : 0;
  int w12 = warp - wdir*12;
  int m0 = (w12 & 3)*16, n0 = (w12 >> 2)*8;
  int arow = m0 + (lane & 7) + ((lane >> 3) & 1)*8;
  int acol = (lane >> 4)*8;
  unsigned sH_base = (unsigned)__cvta_generic_to_shared(sH16);
  unsigned aaddr0 = sH_base + (unsigned)(wdir*64*520 + arow*520 + acol)*2u;
  const __half* bptr = &sW16[wdir*24*520 + (n0 + (lane>>2))*520 + (lane&3)*2];
  float* sGw = sG + wdir*64*26;
  // update identities: fwd = tid in [0,256), bwd = tid in [384,640)
  int udir = (tid >= 384) ? 1 : 0;
  int ut = tid - udir*384;
  bool uvalid = (ut < 256);
  int jl0 = (ut >> 6) & 3, bb0 = ut & 63;
  const float* bh = udir ? bhb : bhf;
  float b_r0=0,b_z0=0,b_n0=0,b_r1=0,b_z1=0,b_n1=0;
  int L_u = S;
  if (uvalid){
    b_r0 = bh[j0+jl0];   b_z0 = bh[512+j0+jl0];   b_n0 = bh[1024+j0+jl0];
    b_r1 = bh[j0+jl0+4]; b_z1 = bh[512+j0+jl0+4]; b_n1 = bh[1024+j0+jl0+4];
    L_u = __ldg(&lens[bb0]);
  }
  float* sGu = sG + udir*64*26;
  gbar();
  float hold0 = 0.f, hold1 = 0.f;
  for (int t = 0; t < S; t++){
    int rb = t & 1, wb = 1 - rb;
    bool v = uvalid && (t < L_u);
    int pos = udir ? (L_u-1-t) : t;
    float xr0=0,xz0=0,xn0=0,xr1=0,xz1=0,xn1=0;
    if (v){
      size_t xb = ((size_t)bb0*S + pos)*NPROJ + (size_t)udir*1536 + j0;
      xr0 = __ldg(&g_XP[xb + jl0]);        xr1 = __ldg(&g_XP[xb + jl0 + 4]);
      xz0 = __ldg(&g_XP[xb + 512 + jl0]);  xz1 = __ldg(&g_XP[xb + 512 + jl0 + 4]);
      xn0 = __ldg(&g_XP[xb + 1024 + jl0]); xn1 = __ldg(&g_XP[xb + 1024 + jl0 + 4]);
    }
    // stage h for BOTH dirs, 2 commit groups by K-half.
    // group layout: idx over [dir(2)][batch(64)][u(32)], u = 16B unit within half
    #pragma unroll
    for (int g = 0; g < 2; g++){
      #pragma unroll
      for (int q = 0; q < 6; q++){
        int idx = q*768 + tid;
        if (idx < 4096){
          int d = idx >> 11;
          int rem = idx & 2047;
          int b = rem >> 5, u = (rem & 31) + g*32;
          cpasync16(sH_base + (unsigned)(d*64*520 + b*520 + u*8)*2u,
                    &g_ht16[rb][d][b][u*8]);
        }
      }
      asm volatile("cp.async.commit_group;" ::: "memory");
    }
    float c[4] = {0.f, 0.f, 0.f, 0.f};
    asm volatile("cp.async.wait_group 1;" ::: "memory");
    __syncthreads();
    #pragma unroll 8
    for (int i = 0; i < 16; i++){
      unsigned a0,a1,a2,a3;
      asm volatile("ldmatrix.sync.aligned.m8n8.x4.shared.b16 {%0,%1,%2,%3}, [%4];"
        : "=r"(a0), "=r"(a1), "=r"(a2), "=r"(a3)
        : "r"(aaddr0 + (unsigned)i*32u));
      unsigned bf0 = *(const unsigned*)(bptr + i*16);
      unsigned bf1 = *(const unsigned*)(bptr + i*16 + 8);
      unsigned a[4] = {a0,a1,a2,a3};
      unsigned bb2[2] = {bf0,bf1};
      mma16(c, a, bb2);
    }
    asm volatile("cp.async.wait_group 0;" ::: "memory");
    __syncthreads();
    #pragma unroll 8
    for (int i = 16; i < 32; i++){
      unsigned a0,a1,a2,a3;
      asm volatile("ldmatrix.sync.aligned.m8n8.x4.shared.b16 {%0,%1,%2,%3}, [%4];"
        : "=r"(a0), "=r"(a1), "=r"(a2), "=r"(a3)
        : "r"(aaddr0 + (unsigned)i*32u));
      unsigned bf0 = *(const unsigned*)(bptr + i*16);
      unsigned bf1 = *(const unsigned*)(bptr + i*16 + 8);
      unsigned a[4] = {a0,a1,a2,a3};
      unsigned bb2[2] = {bf0,bf1};
      mma16(c, a, bb2);
    }
    {
      int mA = m0 + (lane>>2), nA = n0 + (lane&3)*2;
      *(float2*)&sGw[mA*26 + nA]     = make_float2(c[0], c[1]);
      *(float2*)&sGw[(mA+8)*26 + nA] = make_float2(c[2], c[3]);
    }
    __syncthreads();
    float hn0 = hold0, hn1 = hold1;
    if (v){
      float gr = sGu[bb0*26 + jl0]      + b_r0;
      float gz = sGu[bb0*26 + 8 + jl0]  + b_z0;
      float gn = sGu[bb0*26 + 16 + jl0] + b_n0;
      float rr = 1.f/(1.f+expf(-(xr0+gr)));
      float zz = 1.f/(1.f+expf(-(xz0+gz)));
      float nn = tanhf(xn0 + rr*gn);
      hn0 = (1.f-zz)*nn + zz*hold0;
      g_ctx[((size_t)bb0*S+pos)*1024 + (size_t)udir*512 + j0 + jl0] = hn0;
      gr = sGu[bb0*26 + jl0 + 4]      + b_r1;
      gz = sGu[bb0*26 + 8 + jl0 + 4]  + b_z1;
      gn = sGu[bb0*26 + 16 + jl0 + 4] + b_n1;
      rr = 1.f/(1.f+expf(-(xr1+gr)));
      zz = 1.f/(1.f+expf(-(xz1+gz)));
      nn = tanhf(xn1 + rr*gn);
      hn1 = (1.f-zz)*nn + zz*hold1;
      g_ctx[((size_t)bb0*S+pos)*1024 + (size_t)udir*512 + j0 + jl0 + 4] = hn1;
    }
    hold0 = hn0; hold1 = hn1;
    if (uvalid){
      g_ht16[wb][udir][bb0][j0+jl0]   = __float2half(hn0);
      g_ht16[wb][udir][bb0][j0+jl0+4] = __float2half(hn1);
    }
    gbar();
  }
  if (uvalid){
    out[POOL + (size_t)udir*B*H + (size_t)bb0*H + j0 + jl0]     = hold0;
    out[POOL + (size_t)udir*B*H + (size_t)bb0*H + j0 + jl0 + 4] = hold1;
  }
}

__global__ void k_segmax(const int* __restrict__ layout, float* __restrict__ out){
  int bs = blockIdx.x;
  int b = bs >> 6, s = bs & 63;
  int lo = layout[b*(NSEG+1) + s], hi = layout[b*(NSEG+1) + s + 1];
  int tid = threadIdx.x;
  #pragma unroll
  for (int q = 0; q < 4; q++){
    int c = tid + q*256;
    float m = -INFINITY;
    for (int t = lo; t < hi; t++)
      m = fmaxf(m, g_ctx[((size_t)b*S + t)*1024 + c]);
    out[(size_t)bs*1024 + c] = m;
  }
}

extern "C" void kernel_launch(void* const* d_in, const int* in_sizes, int n_in,
                              void* d_out, int out_size){
  (void)in_sizes; (void)n_in; (void)out_size;
  const int*   seq    = (const int*)d_in[0];
  const int*   lens   = (const int*)d_in[1];
  const int*   layout = (const int*)d_in[3];
  const float* emb    = (const float*)d_in[4];
  const float* wif    = (const float*)d_in[5];
  const float* whf    = (const float*)d_in[6];
  const float* bif    = (const float*)d_in[7];
  const float* bhf    = (const float*)d_in[8];
  const float* wib    = (const float*)d_in[9];
  const float* whb    = (const float*)d_in[10];
  const float* bib    = (const float*)d_in[11];
  const float* bhb    = (const float*)d_in[12];
  float* out = (float*)d_out;

  k_embed<<<MR*128/256, 256>>>(seq, emb);
  dim3 gg(48, 256);
  k_gemm<<<gg, 256>>>(wif, wib, bif, bib);
  int smem = (2*24*520 + 2*64*520)*2 + 2*64*26*4;
  cudaFuncSetAttribute(k_scan, cudaFuncAttributeMaxDynamicSharedMemorySize, smem);
  k_scan<<<NBLK, 768, smem>>>(lens, whf, whb, bhf, bhb, out);
  k_segmax<<<B*NSEG, 256>>>(layout, out);
}